// round 5
// baseline (speedup 1.0000x reference)
#include <cuda_runtime.h>
#include <cstdint>

// ScalarRoPEEmbedding:
//   positions:      int32 [8, 8192]
//   sin_cos_cache:  fp32  [10000, 256, 2]   row = 512 floats = 128 float4
//   out:            fp32  [8, 8192, 512]
// out row = cache row with each (sin,cos) float pair swapped.
//
// One warp handles FOUR output rows. Each lane front-batches 16 independent
// float4 gathers (MLP=16) with ld.global.cg (L2-only: gather data has no L1
// reuse), swaps pairs in registers, and writes with st.global.cs streaming
// stores (keep the 20MB table L2-resident against the 134MB output stream).

static constexpr int ROW_VEC4 = 128;     // float4 per 512-dim row
static constexpr int N_ROWS   = 8 * 8192;
static constexpr int ROWS_PER_WARP = 4;
static constexpr int THREADS  = 256;
static constexpr int WARPS_PER_BLOCK = THREADS / 32;

__device__ __forceinline__ float4 ldcg(const float4* p) {
    float4 v;
    asm volatile("ld.global.cg.v4.f32 {%0,%1,%2,%3}, [%4];"
                 : "=f"(v.x), "=f"(v.y), "=f"(v.z), "=f"(v.w) : "l"(p));
    return v;
}

__device__ __forceinline__ void stcs(float4* p, float4 v) {
    asm volatile("st.global.cs.v4.f32 [%0], {%1,%2,%3,%4};"
                 :: "l"(p), "f"(v.x), "f"(v.y), "f"(v.z), "f"(v.w) : "memory");
}

__device__ __forceinline__ float4 swap_pairs(float4 v) {
    float4 o;
    o.x = v.y; o.y = v.x; o.z = v.w; o.w = v.z;
    return o;
}

__global__ void __launch_bounds__(THREADS)
rope_gather_kernel(const int* __restrict__ positions,
                   const float4* __restrict__ cache,
                   float4* __restrict__ out)
{
    const int warp_global = blockIdx.x * WARPS_PER_BLOCK + (threadIdx.x >> 5);
    const int lane        = threadIdx.x & 31;

    const int row_base = warp_global * ROWS_PER_WARP;

    // Warp-uniform position loads (same address per warp -> broadcast)
    int pos[ROWS_PER_WARP];
#pragma unroll
    for (int r = 0; r < ROWS_PER_WARP; r++)
        pos[r] = positions[row_base + r];

    const float4* src[ROWS_PER_WARP];
    float4*       dst[ROWS_PER_WARP];
#pragma unroll
    for (int r = 0; r < ROWS_PER_WARP; r++) {
        src[r] = cache + (long long)pos[r] * ROW_VEC4 + lane;
        dst[r] = out + (long long)(row_base + r) * ROW_VEC4 + lane;
    }

    // Front-batch 16 independent gathers (MLP=16)
    float4 v[ROWS_PER_WARP][4];
#pragma unroll
    for (int r = 0; r < ROWS_PER_WARP; r++)
#pragma unroll
        for (int c = 0; c < 4; c++)
            v[r][c] = ldcg(src[r] + c * 32);

#pragma unroll
    for (int r = 0; r < ROWS_PER_WARP; r++)
#pragma unroll
        for (int c = 0; c < 4; c++)
            stcs(dst[r] + c * 32, swap_pairs(v[r][c]));
}

extern "C" void kernel_launch(void* const* d_in, const int* in_sizes, int n_in,
                              void* d_out, int out_size)
{
    const int*    positions = (const int*)d_in[0];
    const float4* cache     = (const float4*)d_in[1];
    float4*       out       = (float4*)d_out;

    const int rows_per_block = ROWS_PER_WARP * WARPS_PER_BLOCK;  // 32
    const int blocks = N_ROWS / rows_per_block;                  // 2048
    rope_gather_kernel<<<blocks, THREADS>>>(positions, cache, out);
}

// round 7
// speedup vs baseline: 1.0115x; 1.0115x over previous
#include <cuda_runtime.h>
#include <cstdint>

// ScalarRoPEEmbedding:
//   positions:      int32 [8, 8192]
//   sin_cos_cache:  fp32  [10000, 256, 2]   row = 512 floats = 128 float4
//   out:            fp32  [8, 8192, 512]
// out row = cache row with each (sin,cos) float pair swapped.
//
// R5: ROWS_PER_WARP=2 (regs ~40 -> high occupancy) + ld.global.cg gathers
// (no L1 allocation; gather has zero L1 reuse) + st.global.cs streaming
// stores (keep 20MB table L2-resident against the 134MB output stream).
// 32-bit indexing throughout (max float4 index 8.4M fits int).

static constexpr int ROW_VEC4 = 128;     // float4 per 512-dim row
static constexpr int N_ROWS   = 8 * 8192;
static constexpr int ROWS_PER_WARP = 2;
static constexpr int THREADS  = 256;
static constexpr int WARPS_PER_BLOCK = THREADS / 32;

__device__ __forceinline__ float4 ldcg(const float4* p) {
    float4 v;
    asm volatile("ld.global.cg.v4.f32 {%0,%1,%2,%3}, [%4];"
                 : "=f"(v.x), "=f"(v.y), "=f"(v.z), "=f"(v.w) : "l"(p));
    return v;
}

__device__ __forceinline__ void stcs(float4* p, float4 v) {
    asm volatile("st.global.cs.v4.f32 [%0], {%1,%2,%3,%4};"
                 :: "l"(p), "f"(v.x), "f"(v.y), "f"(v.z), "f"(v.w) : "memory");
}

__device__ __forceinline__ float4 swap_pairs(float4 v) {
    float4 o;
    o.x = v.y; o.y = v.x; o.z = v.w; o.w = v.z;
    return o;
}

__global__ void __launch_bounds__(THREADS)
rope_gather_kernel(const int* __restrict__ positions,
                   const float4* __restrict__ cache,
                   float4* __restrict__ out)
{
    const int warp_global = blockIdx.x * WARPS_PER_BLOCK + (threadIdx.x >> 5);
    const int lane        = threadIdx.x & 31;

    const int row0 = warp_global * ROWS_PER_WARP;
    const int row1 = row0 + 1;

    const int pos0 = positions[row0];   // warp-uniform -> broadcast
    const int pos1 = positions[row1];

    const float4* __restrict__ src0 = cache + pos0 * ROW_VEC4 + lane;
    const float4* __restrict__ src1 = cache + pos1 * ROW_VEC4 + lane;
    float4* __restrict__ dst0 = out + row0 * ROW_VEC4 + lane;
    float4* __restrict__ dst1 = out + row1 * ROW_VEC4 + lane;

    // Front-batch 8 independent gathers (MLP=8), L2-only
    float4 a0 = ldcg(src0);
    float4 a1 = ldcg(src0 + 32);
    float4 a2 = ldcg(src0 + 64);
    float4 a3 = ldcg(src0 + 96);
    float4 b0 = ldcg(src1);
    float4 b1 = ldcg(src1 + 32);
    float4 b2 = ldcg(src1 + 64);
    float4 b3 = ldcg(src1 + 96);

    stcs(dst0,      swap_pairs(a0));
    stcs(dst0 + 32, swap_pairs(a1));
    stcs(dst0 + 64, swap_pairs(a2));
    stcs(dst0 + 96, swap_pairs(a3));
    stcs(dst1,      swap_pairs(b0));
    stcs(dst1 + 32, swap_pairs(b1));
    stcs(dst1 + 64, swap_pairs(b2));
    stcs(dst1 + 96, swap_pairs(b3));
}

extern "C" void kernel_launch(void* const* d_in, const int* in_sizes, int n_in,
                              void* d_out, int out_size)
{
    const int*    positions = (const int*)d_in[0];
    const float4* cache     = (const float4*)d_in[1];
    float4*       out       = (float4*)d_out;

    const int rows_per_block = ROWS_PER_WARP * WARPS_PER_BLOCK;  // 16
    const int blocks = N_ROWS / rows_per_block;                  // 4096
    rope_gather_kernel<<<blocks, THREADS>>>(positions, cache, out);
}